// round 10
// baseline (speedup 1.0000x reference)
#include <cuda_runtime.h>

// RNNModel: 2-layer tanh RNN + FC, B=2048, T=512, I=8, H=64.
// R9: two kernels.
//  A) pre_kernel: pre0[e][t][j] = x_t . W_ih0^T + (b_ih0+b_hh0) -> 256MB scratch.
//  B) rnn_q4_kernel: 1 block = 128 thr = 4 warps = 1 element; 4 blocks/SM target.
//     lane = (q = lane>>3, jl = lane&7): 2 rows (j = warp*16+2jl, +1) x 16-k slice
//     of Whh0/Wih1/Whh1 in regs (96). 8 broadcast LDS.128/warp/step (half of R5).
//     k-reduce: shfl.xor(8)+(16) butterfly. Lag-1 layer pipeline, 1 bar/step,
//     unroll x2 parity. h quarters padded (stride 20 floats) -> conflict-free.

#define TT 512
#define HH 64
#define BB 2048
#define HQ 20                 // padded quarter stride (floats)
#define HBUF 80               // per h-vector buffer (floats)
#define FULLMASK 0xffffffffu

typedef unsigned long long ull;

__device__ float g_pre0[(size_t)BB * TT * HH];   // 256 MB scratch (static)

__device__ __forceinline__ ull ffma2(ull a, ull b, ull c) {
    ull d; asm("fma.rn.f32x2 %0, %1, %2, %3;" : "=l"(d) : "l"(a), "l"(b), "l"(c)); return d;
}
__device__ __forceinline__ ull fadd2(ull a, ull b) {
    ull d; asm("add.rn.f32x2 %0, %1, %2;" : "=l"(d) : "l"(a), "l"(b)); return d;
}
__device__ __forceinline__ float hsum1(ull a) {
    float2 f; asm("mov.b64 {%0, %1}, %2;" : "=f"(f.x), "=f"(f.y) : "l"(a));
    return f.x + f.y;
}
__device__ __forceinline__ float hsum2(ull a, ull b) { return hsum1(fadd2(a, b)); }
__device__ __forceinline__ float fast_tanh(float x) {
    // tanh(x) = 1 - 2/(exp(2x)+1); ex2 limits give exactly +-1, no clamp needed.
    float e; asm("ex2.approx.f32 %0, %1;" : "=f"(e) : "f"(x * 2.8853900817779268f));
    float r; asm("rcp.approx.f32 %0, %1;" : "=f"(r) : "f"(e + 1.f));
    return fmaf(-2.f, r, 1.f);
}

// ---------------- Kernel A: x-projection precompute ----------------
__global__ void __launch_bounds__(512)
pre_kernel(const float* __restrict__ x,
           const float* __restrict__ W_ih0,
           const float* __restrict__ b_ih0,
           const float* __restrict__ b_hh0)
{
    const int e  = blockIdx.x;
    const int j  = threadIdx.x & 63;
    const int tq = threadIdx.x >> 6;         // 0..7

    const float* wr = W_ih0 + j * 8;
    float w0 = wr[0], w1 = wr[1], w2 = wr[2], w3 = wr[3];
    float w4 = wr[4], w5 = wr[5], w6 = wr[6], w7 = wr[7];
    const float b = b_ih0[j] + b_hh0[j];

    const float4* xe = (const float4*)(x + (size_t)e * TT * 8);
    float* pe = g_pre0 + (size_t)e * TT * HH;

    for (int t = tq; t < TT; t += 8) {
        float4 xa = xe[2 * t], xb = xe[2 * t + 1];
        float s = b;
        s = fmaf(xa.x, w0, s); s = fmaf(xa.y, w1, s);
        s = fmaf(xa.z, w2, s); s = fmaf(xa.w, w3, s);
        s = fmaf(xb.x, w4, s); s = fmaf(xb.y, w5, s);
        s = fmaf(xb.z, w6, s); s = fmaf(xb.w, w7, s);
        pe[t * HH + j] = s;
    }
}

// ---------------- Kernel B: fused recurrence ----------------
__global__ void __launch_bounds__(128, 4)
rnn_q4_kernel(const float* __restrict__ W_hh0,
              const float* __restrict__ W_ih1,
              const float* __restrict__ W_hh1,
              const float* __restrict__ b_ih1,
              const float* __restrict__ b_hh1,
              const float* __restrict__ fc_w,
              const float* __restrict__ fc_b,
              float* __restrict__ out)
{
    // hb[0],hb[1]: h0 parity buffers; hb[2],hb[3]: h1 parity buffers.
    __shared__ __align__(16) float hb[4][HBUF];
    __shared__ float sfc[4];

    const int tid  = threadIdx.x;
    const int warp = tid >> 5;
    const int lane = tid & 31;
    const int q    = lane >> 3;              // k-quarter: k in [16q, 16q+16)
    const int jl   = lane & 7;
    const int j0   = (warp << 4) | (jl << 1);
    const int j1   = j0 | 1;
    const int e    = blockIdx.x;

    const int qoff = q * HQ;                 // read offset (floats)
    const int woff = warp * HQ + (jl << 1);  // store offset (floats)

    if (tid < HBUF) hb[3][tid] = 0.f;        // h1[-1] buffer

    // ---- Weights: 2 rows x 16-k slice of each matrix (8 ull per row) ----
    ull whh0a[8], whh0b[8], wih1a[8], wih1b[8], whh1a[8], whh1b[8];
#define LOADW(dst, W, row)                                                    \
    {                                                                         \
        const ulonglong2* p = (const ulonglong2*)((W) + (row) * HH + q * 16); \
        ulonglong2 v;                                                         \
        v = p[0]; dst[0] = v.x; dst[1] = v.y;                                 \
        v = p[1]; dst[2] = v.x; dst[3] = v.y;                                 \
        v = p[2]; dst[4] = v.x; dst[5] = v.y;                                 \
        v = p[3]; dst[6] = v.x; dst[7] = v.y;                                 \
    }
    LOADW(whh0a, W_hh0, j0) LOADW(whh0b, W_hh0, j1)
    LOADW(wih1a, W_ih1, j0) LOADW(wih1b, W_ih1, j1)
    LOADW(whh1a, W_hh1, j0) LOADW(whh1b, W_hh1, j1)
#undef LOADW

    const float b1a = b_ih1[j0] + b_hh1[j0];
    const float b1b = b_ih1[j1] + b_hh1[j1];

    // pre0 pairs for this lane: float2 index (t*32 + warp*8 + jl) within element.
    const float2* pbase = (const float2*)(g_pre0 + (size_t)e * TT * HH);
    const float2* prep  = pbase + (warp << 3) + jl;   // t = 0

    // ---- Peel i=0: h0[0] = tanh(pre0[0]) ----
    {
        float2 p0 = prep[0];
        float h0a = fast_tanh(p0.x);
        float h0b = fast_tanh(p0.y);
        if (q == 0) *(float2*)(hb[0] + woff) = make_float2(h0a, h0b);
    }
    float2 pre = prep[32];                   // pre0[1]
    prep += 64;                              // -> pre0[2]
    __syncthreads();

    float h1a = 0.f, h1b = 0.f;

    // STEP: compute h0[i] (reads h0 buf RH0, uses pre) and h1[i-1]
    // (reads RH0 and h1 buf RH1); writes WH0/WH1; one barrier.
#define STEP(RH0, RH1, WH0, WH1, PF)                                          \
    {                                                                         \
        float2 npre;                                                          \
        if (PF) { npre = prep[0]; prep += 32; }                               \
        const ulonglong2* hp0 = (const ulonglong2*)(hb[RH0] + qoff);          \
        const ulonglong2* hp1 = (const ulonglong2*)(hb[RH1] + qoff);          \
        ulonglong2 g0 = hp0[0], g1 = hp0[1], g2 = hp0[2], g3 = hp0[3];        \
        ulonglong2 f0 = hp1[0], f1 = hp1[1], f2 = hp1[2], f3 = hp1[3];        \
        ull a0, b0, c0, c1, d0, d1;                                           \
        a0 = ffma2(g0.x, whh0a[0], 0ull); b0 = ffma2(g0.x, whh0b[0], 0ull);   \
        c0 = ffma2(g0.x, wih1a[0], 0ull); d0 = ffma2(g0.x, wih1b[0], 0ull);   \
        c1 = ffma2(f0.x, whh1a[0], 0ull); d1 = ffma2(f0.x, whh1b[0], 0ull);   \
        a0 = ffma2(g0.y, whh0a[1], a0);   b0 = ffma2(g0.y, whh0b[1], b0);     \
        c0 = ffma2(g0.y, wih1a[1], c0);   d0 = ffma2(g0.y, wih1b[1], d0);     \
        c1 = ffma2(f0.y, whh1a[1], c1);   d1 = ffma2(f0.y, whh1b[1], d1);     \
        a0 = ffma2(g1.x, whh0a[2], a0);   b0 = ffma2(g1.x, whh0b[2], b0);     \
        c0 = ffma2(g1.x, wih1a[2], c0);   d0 = ffma2(g1.x, wih1b[2], d0);     \
        c1 = ffma2(f1.x, whh1a[2], c1);   d1 = ffma2(f1.x, whh1b[2], d1);     \
        a0 = ffma2(g1.y, whh0a[3], a0);   b0 = ffma2(g1.y, whh0b[3], b0);     \
        c0 = ffma2(g1.y, wih1a[3], c0);   d0 = ffma2(g1.y, wih1b[3], d0);     \
        c1 = ffma2(f1.y, whh1a[3], c1);   d1 = ffma2(f1.y, whh1b[3], d1);     \
        a0 = ffma2(g2.x, whh0a[4], a0);   b0 = ffma2(g2.x, whh0b[4], b0);     \
        c0 = ffma2(g2.x, wih1a[4], c0);   d0 = ffma2(g2.x, wih1b[4], d0);     \
        c1 = ffma2(f2.x, whh1a[4], c1);   d1 = ffma2(f2.x, whh1b[4], d1);     \
        a0 = ffma2(g2.y, whh0a[5], a0);   b0 = ffma2(g2.y, whh0b[5], b0);     \
        c0 = ffma2(g2.y, wih1a[5], c0);   d0 = ffma2(g2.y, wih1b[5], d0);     \
        c1 = ffma2(f2.y, whh1a[5], c1);   d1 = ffma2(f2.y, whh1b[5], d1);     \
        a0 = ffma2(g3.x, whh0a[6], a0);   b0 = ffma2(g3.x, whh0b[6], b0);     \
        c0 = ffma2(g3.x, wih1a[6], c0);   d0 = ffma2(g3.x, wih1b[6], d0);     \
        c1 = ffma2(f3.x, whh1a[6], c1);   d1 = ffma2(f3.x, whh1b[6], d1);     \
        a0 = ffma2(g3.y, whh0a[7], a0);   b0 = ffma2(g3.y, whh0b[7], b0);     \
        c0 = ffma2(g3.y, wih1a[7], c0);   d0 = ffma2(g3.y, wih1b[7], d0);     \
        c1 = ffma2(f3.y, whh1a[7], c1);   d1 = ffma2(f3.y, whh1b[7], d1);     \
        float s00 = hsum1(a0);                                                \
        float s01 = hsum1(b0);                                                \
        float s10 = hsum2(c0, c1);                                            \
        float s11 = hsum2(d0, d1);                                            \
        s00 += __shfl_xor_sync(FULLMASK, s00, 8);                             \
        s01 += __shfl_xor_sync(FULLMASK, s01, 8);                             \
        s10 += __shfl_xor_sync(FULLMASK, s10, 8);                             \
        s11 += __shfl_xor_sync(FULLMASK, s11, 8);                             \
        s00 += __shfl_xor_sync(FULLMASK, s00, 16);                            \
        s01 += __shfl_xor_sync(FULLMASK, s01, 16);                            \
        s10 += __shfl_xor_sync(FULLMASK, s10, 16);                            \
        s11 += __shfl_xor_sync(FULLMASK, s11, 16);                            \
        float h0a = fast_tanh(pre.x + s00);                                   \
        float h0b = fast_tanh(pre.y + s01);                                   \
        h1a = fast_tanh(b1a + s10);                                           \
        h1b = fast_tanh(b1b + s11);                                           \
        if (q == 0) *(float2*)(hb[WH0] + woff) = make_float2(h0a, h0b);       \
        if (q == 1) *(float2*)(hb[WH1] + woff) = make_float2(h1a, h1b);       \
        __syncthreads();                                                      \
        if (PF) pre = npre;                                                   \
    }

    // i = 1..510 as 255 unrolled pairs.
    for (int iu = 0; iu < 255; iu++) {
        STEP(0, 3, 1, 2, 1)   // i odd:  h0r=hb0, h1r=hb3 -> h0 hb1, h1 hb2
        STEP(1, 2, 0, 3, 1)   // i even: h0r=hb1, h1r=hb2 -> h0 hb0, h1 hb3
    }
    STEP(0, 3, 1, 2, 0)       // i = 511
#undef STEP

    // ---- Tail: h1[511] from h0[511] (hb1) and h1[510] (hb2) ----
    {
        const ulonglong2* hp0 = (const ulonglong2*)(hb[1] + qoff);
        const ulonglong2* hp1 = (const ulonglong2*)(hb[2] + qoff);
        ulonglong2 g0 = hp0[0], g1 = hp0[1], g2 = hp0[2], g3 = hp0[3];
        ulonglong2 f0 = hp1[0], f1 = hp1[1], f2 = hp1[2], f3 = hp1[3];
        ull c0, c1, d0, d1;
        c0 = ffma2(g0.x, wih1a[0], 0ull); d0 = ffma2(g0.x, wih1b[0], 0ull);
        c1 = ffma2(f0.x, whh1a[0], 0ull); d1 = ffma2(f0.x, whh1b[0], 0ull);
        c0 = ffma2(g0.y, wih1a[1], c0);   d0 = ffma2(g0.y, wih1b[1], d0);
        c1 = ffma2(f0.y, whh1a[1], c1);   d1 = ffma2(f0.y, whh1b[1], d1);
        c0 = ffma2(g1.x, wih1a[2], c0);   d0 = ffma2(g1.x, wih1b[2], d0);
        c1 = ffma2(f1.x, whh1a[2], c1);   d1 = ffma2(f1.x, whh1b[2], d1);
        c0 = ffma2(g1.y, wih1a[3], c0);   d0 = ffma2(g1.y, wih1b[3], d0);
        c1 = ffma2(f1.y, whh1a[3], c1);   d1 = ffma2(f1.y, whh1b[3], d1);
        c0 = ffma2(g2.x, wih1a[4], c0);   d0 = ffma2(g2.x, wih1b[4], d0);
        c1 = ffma2(f2.x, whh1a[4], c1);   d1 = ffma2(f2.x, whh1b[4], d1);
        c0 = ffma2(g2.y, wih1a[5], c0);   d0 = ffma2(g2.y, wih1b[5], d0);
        c1 = ffma2(f2.y, whh1a[5], c1);   d1 = ffma2(f2.y, whh1b[5], d1);
        c0 = ffma2(g3.x, wih1a[6], c0);   d0 = ffma2(g3.x, wih1b[6], d0);
        c1 = ffma2(f3.x, whh1a[6], c1);   d1 = ffma2(f3.x, whh1b[6], d1);
        c0 = ffma2(g3.y, wih1a[7], c0);   d0 = ffma2(g3.y, wih1b[7], d0);
        c1 = ffma2(f3.y, whh1a[7], c1);   d1 = ffma2(f3.y, whh1b[7], d1);
        float s10 = hsum2(c0, c1);
        float s11 = hsum2(d0, d1);
        s10 += __shfl_xor_sync(FULLMASK, s10, 8);
        s11 += __shfl_xor_sync(FULLMASK, s11, 8);
        s10 += __shfl_xor_sync(FULLMASK, s10, 16);
        s11 += __shfl_xor_sync(FULLMASK, s11, 16);
        h1a = fast_tanh(b1a + s10);
        h1b = fast_tanh(b1b + s11);
    }

    // ---- FC ----
    float fa = 0.f, fb = 0.f;
    if (q == 0) { fa = fc_w[j0]; fb = fc_w[j1]; }   // count each j once
    float v = h1a * fa + h1b * fb;
    #pragma unroll
    for (int off = 16; off > 0; off >>= 1)
        v += __shfl_xor_sync(FULLMASK, v, off);
    if (lane == 0) sfc[warp] = v;
    __syncthreads();
    if (tid == 0)
        out[e] = sfc[0] + sfc[1] + sfc[2] + sfc[3] + fc_b[0];
}

extern "C" void kernel_launch(void* const* d_in, const int* in_sizes, int n_in,
                              void* d_out, int out_size)
{
    const float* x     = (const float*)d_in[0];
    const float* W_ih0 = (const float*)d_in[1];
    const float* W_hh0 = (const float*)d_in[2];
    const float* b_ih0 = (const float*)d_in[3];
    const float* b_hh0 = (const float*)d_in[4];
    const float* W_ih1 = (const float*)d_in[5];
    const float* W_hh1 = (const float*)d_in[6];
    const float* b_ih1 = (const float*)d_in[7];
    const float* b_hh1 = (const float*)d_in[8];
    const float* fc_w  = (const float*)d_in[9];
    const float* fc_b  = (const float*)d_in[10];
    float* out = (float*)d_out;

    pre_kernel<<<BB, 512>>>(x, W_ih0, b_ih0, b_hh0);
    rnn_q4_kernel<<<BB, 128>>>(W_hh0, W_ih1, W_hh1,
                               b_ih1, b_hh1, fc_w, fc_b, out);
}

// round 12
// speedup vs baseline: 1.5480x; 1.5480x over previous
#include <cuda_runtime.h>

// RNNModel: 2-layer tanh RNN + FC, B=2048, T=512, I=8, H=64.
// R11: R10 diet kernel with the bias double-count bug fixed.
//  - R10 folded pre-scaled biases into accumulator init on BOTH k-halves;
//    the shfl.xor(16) reduce then summed the bias twice. Fix: bias init only
//    on ks==0 lanes (pb0/pb1 = 0 on ks==1).
//  - Rest identical: weights pre-scaled by 2*log2(e) (tanh multiply-free),
//    x-term split across k-halves, 2-accumulator layer-0 chain,
//    R5 topology (4 warps/elem, in-warp k-split, 1 bar/step, parity unroll x2).

#define TT 512
#define HH 64
#define NTHREADS 128
#define BB 2048
#define FULLMASK 0xffffffffu
#define HROW 72          // 64 + skew pad; half0 at [0,32), half1 at [36,68)
#define LOG2E2 2.8853900817779268f   // 2*log2(e)

typedef unsigned long long ull;

__device__ __forceinline__ ull ffma2(ull a, ull b, ull c) {
    ull d; asm("fma.rn.f32x2 %0, %1, %2, %3;" : "=l"(d) : "l"(a), "l"(b), "l"(c)); return d;
}
__device__ __forceinline__ ull fadd2(ull a, ull b) {
    ull d; asm("add.rn.f32x2 %0, %1, %2;" : "=l"(d) : "l"(a), "l"(b)); return d;
}
__device__ __forceinline__ ull fmul2(ull a, ull b) {
    ull d; asm("mul.rn.f32x2 %0, %1, %2;" : "=l"(d) : "l"(a), "l"(b)); return d;
}
__device__ __forceinline__ ull pack2(float lo, float hi) {
    ull d; asm("mov.b64 %0, {%1, %2};" : "=l"(d) : "f"(lo), "f"(hi)); return d;
}
__device__ __forceinline__ float hsum1(ull a) {
    float2 f; asm("mov.b64 {%0, %1}, %2;" : "=f"(f.x), "=f"(f.y) : "l"(a));
    return f.x + f.y;
}
__device__ __forceinline__ float hsum2(ull a, ull b) { return hsum1(fadd2(a, b)); }
__device__ __forceinline__ float hsum4(ull a0, ull a1, ull a2, ull a3) {
    return hsum1(fadd2(fadd2(a0, a1), fadd2(a2, a3)));
}
// Argument is PRE-SCALED by 2*log2(e): tanh(z) = 1 - 2/(exp2(z*2log2e)+1).
__device__ __forceinline__ float fast_tanh_scaled(float zs) {
    float e; asm("ex2.approx.f32 %0, %1;" : "=f"(e) : "f"(zs));
    float r; asm("rcp.approx.f32 %0, %1;" : "=f"(r) : "f"(e + 1.f));
    return fmaf(-2.f, r, 1.f);
}

__global__ void __launch_bounds__(NTHREADS, 3)
rnn_diet_kernel(const float* __restrict__ x,
                const float* __restrict__ W_ih0,
                const float* __restrict__ W_hh0,
                const float* __restrict__ b_ih0,
                const float* __restrict__ b_hh0,
                const float* __restrict__ W_ih1,
                const float* __restrict__ W_hh1,
                const float* __restrict__ b_ih1,
                const float* __restrict__ b_hh1,
                const float* __restrict__ fc_w,
                const float* __restrict__ fc_b,
                float* __restrict__ out)
{
    __shared__ float s00[HROW];   // h0 parity 0
    __shared__ float s01[HROW];   // h0 parity 1
    __shared__ float s10[HROW];   // h1 parity 0
    __shared__ float s11[HROW];   // h1 parity 1
    __shared__ float sfc[4];

    const int tid  = threadIdx.x;
    const int warp = tid >> 5;
    const int lane = tid & 31;
    const int jl   = lane & 15;
    const int ks   = lane >> 4;              // k half
    const int j    = warp * 16 + jl;
    const int jidx = j + ((j >> 5) << 2);    // skewed store index
    const int khoff = ks * 36;               // skewed read offset (floats)
    const int e    = blockIdx.x;

    if (tid < HROW) { s11[tid] = 0.f; s10[tid] = 0.f; }

    const ull CC = pack2(LOG2E2, LOG2E2);

    // ---- Per-lane half-k weight rows, PRE-SCALED by 2log2e ----
    ull whh0h[16], wih1h[16], whh1h[16], wih0s[2];
    {
        const ulonglong2* p = (const ulonglong2*)(W_hh0 + j * HH + ks * 32);
        #pragma unroll
        for (int i = 0; i < 8; i++) {
            ulonglong2 v = p[i];
            whh0h[2*i] = fmul2(v.x, CC); whh0h[2*i+1] = fmul2(v.y, CC);
        }
    }
    {
        const ulonglong2* p = (const ulonglong2*)(W_ih1 + j * HH + ks * 32);
        #pragma unroll
        for (int i = 0; i < 8; i++) {
            ulonglong2 v = p[i];
            wih1h[2*i] = fmul2(v.x, CC); wih1h[2*i+1] = fmul2(v.y, CC);
        }
    }
    {
        const ulonglong2* p = (const ulonglong2*)(W_hh1 + j * HH + ks * 32);
        #pragma unroll
        for (int i = 0; i < 8; i++) {
            ulonglong2 v = p[i];
            whh1h[2*i] = fmul2(v.x, CC); whh1h[2*i+1] = fmul2(v.y, CC);
        }
    }
    {   // W_ih0 row j, this lane's k-quarter of I=8: cols [ks*4, ks*4+4)
        const ulonglong2* p = (const ulonglong2*)(W_ih0 + j * 8 + ks * 4);
        ulonglong2 v = p[0];
        wih0s[0] = fmul2(v.x, CC); wih0s[1] = fmul2(v.y, CC);
    }

    // Biases pre-scaled, packed as (b, 0) -- ONLY on the ks==0 half, so the
    // cross-half shfl reduce counts each bias exactly once (R10 bug fix).
    ull pb0 = pack2((b_ih0[j] + b_hh0[j]) * LOG2E2, 0.f);
    ull pb1 = pack2((b_ih1[j] + b_hh1[j]) * LOG2E2, 0.f);
    if (ks == 1) { pb0 = 0ull; pb1 = 0ull; }

    float fcw = fc_w[j];
    if (ks == 1) fcw = 0.f;                  // count each j once in FC reduce

    // Hoisted skew-baked read pointers.
    const ulonglong2* pA = (const ulonglong2*)(s00 + khoff);
    const ulonglong2* pB = (const ulonglong2*)(s01 + khoff);
    const ulonglong2* pC = (const ulonglong2*)(s10 + khoff);
    const ulonglong2* pD = (const ulonglong2*)(s11 + khoff);

    __syncthreads();

    // x: lane reads its k-quarter (float4) of step t: index t*2 + ks (ulonglong2).
    const ulonglong2* xp = (const ulonglong2*)(x + (size_t)e * TT * 8) + ks;
    ulonglong2 xq = xp[0];                   // x[0]
    xp += 2;                                 // -> x[1]

    // ---- Peel i=0: h0[0] = tanh(b0 + x0.Wih0) ----
    {
        ull a0 = ffma2(xq.x, wih0s[0], pb0);
        ull a1 = ffma2(xq.y, wih0s[1], 0ull);
        float s0 = hsum2(a0, a1);
        s0 += __shfl_xor_sync(FULLMASK, s0, 16);
        float h0n = fast_tanh_scaled(s0);
        if (ks == 0) s00[jidx] = h0n;
        __syncthreads();
        xq = xp[0]; xp += 2;                 // x[1]
    }

    float h1n = 0.f;

    // Body: compute h0[i] (from H0R = h0[i-1], x[i]) and h1[i-1] (from H0R and
    // H1R = h1[i-2]); store to H0W/H1W; one barrier.
#define STEP_BODY(H0R, H1R, H0W, H1W, PF)                                        \
    {                                                                            \
        ull a0 = ffma2(xq.x, wih0s[0], pb0);                                     \
        ull a1 = ffma2(xq.y, wih0s[1], 0ull);                                    \
        ull c0 = pb1, c1 = 0, c2 = 0, c3 = 0;                                    \
        ulonglong2 nxq;                                                          \
        if (PF) { nxq = xp[0]; xp += 2; }                                        \
        _Pragma("unroll")                                                        \
        for (int q = 0; q < 8; q++) {                                            \
            ulonglong2 hv = H0R[q];                                              \
            a0 = ffma2(hv.x, whh0h[2*q],   a0);                                  \
            a1 = ffma2(hv.y, whh0h[2*q+1], a1);                                  \
            c0 = ffma2(hv.x, wih1h[2*q],   c0);                                  \
            c1 = ffma2(hv.y, wih1h[2*q+1], c1);                                  \
        }                                                                        \
        _Pragma("unroll")                                                        \
        for (int q = 0; q < 8; q++) {                                            \
            ulonglong2 hv = H1R[q];                                              \
            c2 = ffma2(hv.x, whh1h[2*q],   c2);                                  \
            c3 = ffma2(hv.y, whh1h[2*q+1], c3);                                  \
        }                                                                        \
        float s0 = hsum2(a0, a1);                                                \
        s0 += __shfl_xor_sync(FULLMASK, s0, 16);                                 \
        float h0n = fast_tanh_scaled(s0);                                        \
        float s1 = hsum4(c0, c1, c2, c3);                                        \
        s1 += __shfl_xor_sync(FULLMASK, s1, 16);                                 \
        h1n = fast_tanh_scaled(s1);                                              \
        if (ks == 0) H0W[jidx] = h0n;                                            \
        else         H1W[jidx] = h1n;                                            \
        __syncthreads();                                                         \
        if (PF) xq = nxq;                                                        \
    }

    // i = 1..510 as 255 unrolled pairs (odd parity then even parity).
    for (int iu = 0; iu < 255; iu++) {
        STEP_BODY(pA, pD, s01, s10, 1);   // i odd:  h0r=s00, h1r=s11 -> s01, s10
        STEP_BODY(pB, pC, s00, s11, 1);   // i even: h0r=s01, h1r=s10 -> s00, s11
    }
    STEP_BODY(pA, pD, s01, s10, 0);       // i = 511
#undef STEP_BODY

    // ---- Tail: h1[511] from h0[511] (s01) and h1[510] (s10) ----
    {
        ull c0 = pb1, c1 = 0, c2 = 0, c3 = 0;
        #pragma unroll
        for (int q = 0; q < 8; q++) {
            ulonglong2 hv = pB[q];
            c0 = ffma2(hv.x, wih1h[2*q],   c0);
            c1 = ffma2(hv.y, wih1h[2*q+1], c1);
        }
        #pragma unroll
        for (int q = 0; q < 8; q++) {
            ulonglong2 hv = pC[q];
            c2 = ffma2(hv.x, whh1h[2*q],   c2);
            c3 = ffma2(hv.y, whh1h[2*q+1], c3);
        }
        float s1 = hsum4(c0, c1, c2, c3);
        s1 += __shfl_xor_sync(FULLMASK, s1, 16);
        h1n = fast_tanh_scaled(s1);
    }

    // ---- FC: out[e] = sum_j h1_last[j] * fc_w[j] + fc_b ----
    float v = h1n * fcw;                     // fcw==0 on ks=1 lanes
    #pragma unroll
    for (int off = 16; off > 0; off >>= 1)
        v += __shfl_xor_sync(FULLMASK, v, off);
    if (lane == 0) sfc[warp] = v;
    __syncthreads();
    if (tid == 0)
        out[e] = sfc[0] + sfc[1] + sfc[2] + sfc[3] + fc_b[0];
}

extern "C" void kernel_launch(void* const* d_in, const int* in_sizes, int n_in,
                              void* d_out, int out_size)
{
    const float* x     = (const float*)d_in[0];
    const float* W_ih0 = (const float*)d_in[1];
    const float* W_hh0 = (const float*)d_in[2];
    const float* b_ih0 = (const float*)d_in[3];
    const float* b_hh0 = (const float*)d_in[4];
    const float* W_ih1 = (const float*)d_in[5];
    const float* W_hh1 = (const float*)d_in[6];
    const float* b_ih1 = (const float*)d_in[7];
    const float* b_hh1 = (const float*)d_in[8];
    const float* fc_w  = (const float*)d_in[9];
    const float* fc_b  = (const float*)d_in[10];
    float* out = (float*)d_out;

    dim3 grid(BB);          // 2048 blocks, one batch element each
    dim3 block(NTHREADS);   // 128 threads = 4 warps
    rnn_diet_kernel<<<grid, block>>>(
        x, W_ih0, W_hh0, b_ih0, b_hh0,
        W_ih1, W_hh1, b_ih1, b_hh1,
        fc_w, fc_b, out);
}